// round 14
// baseline (speedup 1.0000x reference)
#include <cuda_runtime.h>
#include <math.h>

#define T_STEPS 2048
#define BATCH   64
#define IN_DIM  128
#define LIQ     512
#define OUT_DIM 128
#define NG      16      // independent groups (4 batches each)
#define GSZ     8       // CTAs per group (64 j's each)

// ---------------- scratch (device globals; no runtime allocation) ----------------
__device__ float g_xw2 [(size_t)T_STEPS * NG * LIQ * 4];   // [t][g][j][bi]
__device__ float g_hall[(size_t)T_STEPS * LIQ * BATCH];    // [t][j][b]
__device__ float g_hx  [2 * NG * 4 * LIQ];                 // [buf][g][bi][k]
__device__ unsigned g_cnt[T_STEPS * NG];                   // per-step group arrivals

// ---------------- XLA EmitFastTanh, with_fma=true configuration (BIT-EXACT) --------
__device__ __forceinline__ float xla_tanhf(float x) {
    const float kClamp = 7.99881172180175781f;
    float xc = fminf(fmaxf(x, -kClamp), kClamp);
    float x2 = __fmul_rn(xc, xc);
    float p = fmaf(x2, -2.76076847742355e-16f, 2.00018790482477e-13f);
    p = fmaf(x2, p, -8.60467152213735e-11f);
    p = fmaf(x2, p,  5.12229709037114e-08f);
    p = fmaf(x2, p,  1.48572235717979e-05f);
    p = fmaf(x2, p,  6.37261928875436e-04f);
    p = fmaf(x2, p,  4.89352455891786e-03f);
    float num = __fmul_rn(xc, p);
    float q = fmaf(x2, 1.19825839466702e-06f, 1.18534705686654e-04f);
    q = fmaf(x2, q, 2.26843463243900e-03f);
    q = fmaf(x2, q, 4.89352518554385e-03f);
    float r = __fdiv_rn(num, q);
    return (fabsf(x) < 0.0004f) ? x : r;
}

// ---------------- stage 1: xw = x_t @ W_x, ascending-k single-acc fmaf chains ------
// (byte-identical to the passing R12 kernel — feeds the bit-exact recurrence)
__global__ void __launch_bounds__(512) xw_kernel(const float* __restrict__ inp,
                                                 const float* __restrict__ W) {
    extern __shared__ float sm[];
    float* xs = sm;           // [64][128]   8192 floats
    float* wt = sm + 8192;    // [128 j][132 k] transposed W_x tile, 16896 floats
    const int t = blockIdx.x, tid = threadIdx.x;

    const float4* in4 = (const float4*)inp;
    float4* xs4 = (float4*)xs;
    for (int m = tid; m < 2048; m += 512) {
        int b = m >> 5, k4 = m & 31;
        xs4[m] = in4[((size_t)b * T_STEPS + t) * 32 + k4];
    }

    const int jl = tid & 127, bq = tid >> 7;

    for (int jt = 0; jt < 4; jt++) {
        __syncthreads();
        for (int i = tid; i < 16384; i += 512) {            // wt[j][k] = W_x[k][jt*128+j]
            int k = i >> 7, jj = i & 127;
            wt[jj * 132 + k] = W[(size_t)k * LIQ + jt * 128 + jj];
        }
        __syncthreads();

        const float* wrow = &wt[jl * 132];
        const int j = jt * 128 + jl;
        for (int ii = 0; ii < 16; ii++) {
            int b = bq * 16 + ii;
            const float* xrow = &xs[b * 128];
            float acc = 0.f;
#pragma unroll
            for (int k = 0; k < 128; k += 4) {              // ascending k, single acc
                float4 xv = *(const float4*)&xrow[k];
                float4 wv = *(const float4*)&wrow[k];
                acc = fmaf(xv.x, wv.x, acc);
                acc = fmaf(xv.y, wv.y, acc);
                acc = fmaf(xv.z, wv.z, acc);
                acc = fmaf(xv.w, wv.w, acc);
            }
            g_xw2[(((size_t)t * NG + (b >> 2)) * LIQ + j) * 4 + (b & 3)] = acc;
        }
    }
}

// ---------------- init ----------------
__global__ void __launch_bounds__(256) init_kernel() {
    int idx = blockIdx.x * 256 + threadIdx.x;    // grid 256 -> 65536
    if (idx < 2 * NG * 4 * LIQ) g_hx[idx] = 0.f;
    if (idx < T_STEPS * NG) g_cnt[idx] = 0u;
}

// ---------------- stage 2: recurrence (bit-exact chains, broadcast-friendly map) ----
// CTA (g, r): batches 4g..4g+3, j in [64r, 64r+64).
// Thread map: jl = tid>>2 (j), b = tid&3. The 4 lanes sharing a j read the SAME
// Wt row -> LDS broadcast; each W row is fetched once per step (W SMEM traffic
// 4x lower than the (tid&63, tid>>6) map). Per-output math is the IDENTICAL
// ascending-k single-accumulator fmaf chain -> bit-exact vs the passing R12.
__global__ void __launch_bounds__(256, 1) recur_kernel(const float* __restrict__ W) {
    extern __shared__ float smem[];
    float* Wt  = smem;              // [64 j][516 k]  33024 floats (transposed W_h slice)
    float* hsm = smem + 33024;      // [4 b][516 k]    2064 floats

    const int tid = threadIdx.x;
    const int g   = (int)(blockIdx.x >> 3);
    const int r   = (int)(blockIdx.x & 7);
    const int j0  = r * 64;

    for (int i = tid; i < 64 * LIQ; i += 256) {              // Wt[j][k] = W[128+k][j0+j]
        int k = i >> 6, jj = i & 63;
        Wt[jj * 516 + k] = W[(size_t)(128 + k) * LIQ + j0 + jj];
    }

    const int jl = tid >> 2;       // j within CTA (0..63)
    const int b  = tid & 3;        // batch within group (0..3)
    const float* wrow = &Wt[jl * 516];
    const float* hrow = &hsm[b * 516];

    for (int t = 0; t < T_STEPS; t++) {
        if (t > 0 && tid == 0) {
            unsigned* cp = &g_cnt[(size_t)(t - 1) * NG + g];
            while (atomicAdd(cp, 0u) != (unsigned)GSZ) { }
        }
        __syncthreads();                                     // bar A (Wt ready at t==0)

        {   // pull group's h (4 x 512 floats, [b][k]) into SMEM
            const float4* src4 = (const float4*)(g_hx + ((size_t)(t & 1) * NG + g) * 2048);
#pragma unroll
            for (int q = 0; q < 2; q++) {
                int idx = q * 256 + tid;
                int bb = idx >> 7, k4 = idx & 127;
                *(float4*)&hsm[bb * 516 + k4 * 4] = __ldcv(&src4[idx]);
            }
        }
        float xwv = g_xw2[(((size_t)t * NG + g) * LIQ + j0 + jl) * 4 + b];
        __syncthreads();                                     // bar B: hsm ready

        float acc = 0.f;
#pragma unroll 16
        for (int k = 0; k < 512; k += 4) {                   // ascending k, single acc
            float4 hv = *(const float4*)&hrow[k];
            float4 wv = *(const float4*)&wrow[k];
            acc = fmaf(hv.x, wv.x, acc);
            acc = fmaf(hv.y, wv.y, acc);
            acc = fmaf(hv.z, wv.z, acc);
            acc = fmaf(hv.w, wv.w, acc);
        }
        float h = xla_tanhf(__fadd_rn(xwv, acc));            // z = xw + hw (single add)

        g_hall[((size_t)t * LIQ + j0 + jl) * BATCH + g * 4 + b] = h;
        g_hx[(((size_t)((t + 1) & 1) * NG + g) * 4 + b) * LIQ + j0 + jl] = h;

        __threadfence();                                     // release (every thread)
        __syncthreads();                                     // bar C: stores done
        if (tid == 0)
            atomicAdd(&g_cnt[(size_t)t * NG + g], 1u);
    }
}

// ---------------- stage 3: readout (unchanged; h bit-correct => err ~1e-7) ---------
__global__ void __launch_bounds__(256) readout_kernel(const float* __restrict__ Wro,
                                                      const float* __restrict__ bro,
                                                      float* __restrict__ out,
                                                      int write_hfinal) {
    extern __shared__ float sm[];
    float* hs = sm;            // [512][64]
    float* ws = sm + 32768;    // [512][32]
    const int t = blockIdx.x, tid = threadIdx.x;

    float4* hs4 = (float4*)hs;
    const float4* hall4 = (const float4*)g_hall + (size_t)t * 8192;
    for (int m = tid; m < 8192; m += 256) hs4[m] = hall4[m];

    const float4* Wro4 = (const float4*)Wro;
    float4* ws4 = (float4*)ws;
    const int oo = tid & 31, bg = tid >> 5;

    for (int ot = 0; ot < 4; ot++) {
        __syncthreads();
        for (int m = tid; m < 4096; m += 256) {
            int j = m >> 3, o4 = m & 7;
            ws4[m] = Wro4[j * 32 + ot * 8 + o4];
        }
        __syncthreads();

        int o = ot * 32 + oo;
        float bias = bro[o];
        float acc[8];
#pragma unroll
        for (int i = 0; i < 8; i++) acc[i] = 0.f;

        for (int k = 0; k < 512; k++) {
            float  w  = ws[k * 32 + oo];
            float4 h0 = hs4[k * 16 + bg * 2];
            float4 h1 = hs4[k * 16 + bg * 2 + 1];
            acc[0] += h0.x * w;  acc[1] += h0.y * w;
            acc[2] += h0.z * w;  acc[3] += h0.w * w;
            acc[4] += h1.x * w;  acc[5] += h1.y * w;
            acc[6] += h1.z * w;  acc[7] += h1.w * w;
        }
#pragma unroll
        for (int i = 0; i < 8; i++) {
            int b = bg * 8 + i;
            out[((size_t)b * T_STEPS + t) * OUT_DIM + o] = acc[i] + bias;
        }
    }

    if (t == T_STEPS - 1 && write_hfinal) {
        __syncthreads();
        const size_t FBASE = (size_t)BATCH * T_STEPS * OUT_DIM;
        for (int m = tid; m < BATCH * LIQ; m += 256) {
            int b = m >> 9, j = m & 511;
            out[FBASE + m] = hs[j * 64 + b];
        }
    }
}

// ---------------- launch ----------------
extern "C" void kernel_launch(void* const* d_in, const int* in_sizes, int n_in,
                              void* d_out, int out_size) {
    const float* inp = nullptr;
    const float* W   = nullptr;
    const float* Wro = nullptr;
    const float* bro = nullptr;
    for (int i = 0; i < n_in; i++) {
        switch (in_sizes[i]) {
            case 16777216: inp = (const float*)d_in[i]; break;
            case 327680:   W   = (const float*)d_in[i]; break;
            case 65536:    Wro = (const float*)d_in[i]; break;
            case 128:      bro = (const float*)d_in[i]; break;
            default: break;
        }
    }
    float* out = (float*)d_out;
    int write_hfinal = (out_size >= BATCH * T_STEPS * OUT_DIM + BATCH * LIQ) ? 1 : 0;

    const int XW_SMEM    = (8192 + 16896) * 4;   // 100352 B
    const int RECUR_SMEM = (33024 + 2064) * 4;   // 140352 B

    cudaFuncSetAttribute(xw_kernel,      cudaFuncAttributeMaxDynamicSharedMemorySize, XW_SMEM);
    cudaFuncSetAttribute(recur_kernel,   cudaFuncAttributeMaxDynamicSharedMemorySize, RECUR_SMEM);
    cudaFuncSetAttribute(readout_kernel, cudaFuncAttributeMaxDynamicSharedMemorySize, 196608);

    xw_kernel<<<T_STEPS, 512, XW_SMEM>>>(inp, W);
    init_kernel<<<256, 256>>>();
    recur_kernel<<<NG * GSZ, 256, RECUR_SMEM>>>(W);
    readout_kernel<<<T_STEPS, 256, 196608>>>(Wro, bro, out, write_hfinal);
}

// round 15
// speedup vs baseline: 1.0273x; 1.0273x over previous
#include <cuda_runtime.h>
#include <math.h>
#include <stdint.h>

#define T_STEPS 2048
#define BATCH   64
#define IN_DIM  128
#define LIQ     512
#define OUT_DIM 128
#define NG      16      // clusters (4 batches each)
#define GSZ     8       // CTAs per cluster (64 j's each)

// ---------------- scratch (device globals; no runtime allocation) ----------------
__device__ float g_xw2 [(size_t)T_STEPS * NG * LIQ * 4];   // [t][g][j][bi]
__device__ float g_hall[(size_t)T_STEPS * LIQ * BATCH];    // [t][j][b]

// ---------------- XLA EmitFastTanh, with_fma=true configuration (BIT-EXACT) --------
__device__ __forceinline__ float xla_tanhf(float x) {
    const float kClamp = 7.99881172180175781f;
    float xc = fminf(fmaxf(x, -kClamp), kClamp);
    float x2 = __fmul_rn(xc, xc);
    float p = fmaf(x2, -2.76076847742355e-16f, 2.00018790482477e-13f);
    p = fmaf(x2, p, -8.60467152213735e-11f);
    p = fmaf(x2, p,  5.12229709037114e-08f);
    p = fmaf(x2, p,  1.48572235717979e-05f);
    p = fmaf(x2, p,  6.37261928875436e-04f);
    p = fmaf(x2, p,  4.89352455891786e-03f);
    float num = __fmul_rn(xc, p);
    float q = fmaf(x2, 1.19825839466702e-06f, 1.18534705686654e-04f);
    q = fmaf(x2, q, 2.26843463243900e-03f);
    q = fmaf(x2, q, 4.89352518554385e-03f);
    float r = __fdiv_rn(num, q);
    return (fabsf(x) < 0.0004f) ? x : r;
}

__device__ __forceinline__ uint32_t smem_u32(const void* p) {
    uint32_t a;
    asm("{ .reg .u64 t; cvta.to.shared.u64 t, %1; cvt.u32.u64 %0, t; }"
        : "=r"(a) : "l"(p));
    return a;
}

// ---------------- stage 1: xw = x_t @ W_x (byte-identical to passing R12) ----------
__global__ void __launch_bounds__(512) xw_kernel(const float* __restrict__ inp,
                                                 const float* __restrict__ W) {
    extern __shared__ float sm[];
    float* xs = sm;           // [64][128]   8192 floats
    float* wt = sm + 8192;    // [128 j][132 k] transposed W_x tile, 16896 floats
    const int t = blockIdx.x, tid = threadIdx.x;

    const float4* in4 = (const float4*)inp;
    float4* xs4 = (float4*)xs;
    for (int m = tid; m < 2048; m += 512) {
        int b = m >> 5, k4 = m & 31;
        xs4[m] = in4[((size_t)b * T_STEPS + t) * 32 + k4];
    }

    const int jl = tid & 127, bq = tid >> 7;

    for (int jt = 0; jt < 4; jt++) {
        __syncthreads();
        for (int i = tid; i < 16384; i += 512) {            // wt[j][k] = W_x[k][jt*128+j]
            int k = i >> 7, jj = i & 127;
            wt[jj * 132 + k] = W[(size_t)k * LIQ + jt * 128 + jj];
        }
        __syncthreads();

        const float* wrow = &wt[jl * 132];
        const int j = jt * 128 + jl;
        for (int ii = 0; ii < 16; ii++) {
            int b = bq * 16 + ii;
            const float* xrow = &xs[b * 128];
            float acc = 0.f;
#pragma unroll
            for (int k = 0; k < 128; k += 4) {              // ascending k, single acc
                float4 xv = *(const float4*)&xrow[k];
                float4 wv = *(const float4*)&wrow[k];
                acc = fmaf(xv.x, wv.x, acc);
                acc = fmaf(xv.y, wv.y, acc);
                acc = fmaf(xv.z, wv.z, acc);
                acc = fmaf(xv.w, wv.w, acc);
            }
            g_xw2[(((size_t)t * NG + (b >> 2)) * LIQ + j) * 4 + (b & 3)] = acc;
        }
    }
}

// ---------------- stage 2: recurrence — R12 bit-exact compute, DSMEM exchange ------
// 16 clusters of 8 CTAs. CTA (g = bid>>3, r = bid&7): batches 4g..4g+3,
// j in [64r, 64r+64). Thread map EXACTLY R12: jl = tid&63, b = tid>>6.
// Exchange: after computing h, each thread pushes it into ALL 8 cluster CTAs'
// hsm (double-buffered) via mapa + st.shared::cluster, then one
// barrier.cluster.arrive/wait per step (g_hall store overlapped in between).
// No L2 pulls, no fences, no atomic spin. Values identical -> bit-exact.
__global__ void __launch_bounds__(256, 1) __cluster_dims__(GSZ, 1, 1)
recur_kernel(const float* __restrict__ W) {
    extern __shared__ float smem[];
    float* Wt  = smem;              // [64 j][516 k]    33024 floats
    float* hsm = smem + 33024;      // [2 buf][4 b][516] 4128 floats

    const int tid = threadIdx.x;
    const int g   = (int)(blockIdx.x >> 3);
    const int r   = (int)(blockIdx.x & 7);
    const int j0  = r * 64;

    for (int i = tid; i < 64 * LIQ; i += 256) {              // Wt[j][k] = W[128+k][j0+j]
        int k = i >> 6, jj = i & 63;
        Wt[jj * 516 + k] = W[(size_t)(128 + k) * LIQ + j0 + jj];
    }
    for (int i = tid; i < 2 * 4 * 516; i += 256) hsm[i] = 0.f;   // h0 = 0 (both bufs)
    __syncthreads();
    // peers' SMEM initialized before any st.shared::cluster may target it
    asm volatile("barrier.cluster.arrive.aligned;" ::: "memory");
    asm volatile("barrier.cluster.wait.aligned;"   ::: "memory");

    const int jl = tid & 63;       // j within CTA (R12 map — do not change)
    const int b  = tid >> 6;       // batch within group
    const float* wrow = &Wt[jl * 516];
    const uint32_t hbase = smem_u32(hsm);

    for (int t = 0; t < T_STEPS; t++) {
        const float* hrow = &hsm[(t & 1) * 2064 + b * 516];
        const int nb = (t + 1) & 1;

        float xwv = g_xw2[(((size_t)t * NG + g) * LIQ + j0 + jl) * 4 + b];

        float acc = 0.f;
#pragma unroll 16
        for (int k = 0; k < 512; k += 4) {                   // ascending k, single acc
            float4 hv = *(const float4*)&hrow[k];
            float4 wv = *(const float4*)&wrow[k];
            acc = fmaf(hv.x, wv.x, acc);
            acc = fmaf(hv.y, wv.y, acc);
            acc = fmaf(hv.z, wv.z, acc);
            acc = fmaf(hv.w, wv.w, acc);
        }
        float h = xla_tanhf(__fadd_rn(xwv, acc));            // z = xw + hw (single add)

        // push h into buffer nb of ALL 8 cluster CTAs (incl. self) via DSMEM
        uint32_t loff = hbase + (uint32_t)((nb * 2064 + b * 516 + j0 + jl) * 4);
#pragma unroll
        for (int rr = 0; rr < GSZ; rr++) {
            uint32_t ra;
            asm("mapa.shared::cluster.u32 %0, %1, %2;" : "=r"(ra) : "r"(loff), "r"(rr));
            asm volatile("st.shared::cluster.f32 [%0], %1;" :: "r"(ra), "f"(h));
        }
        asm volatile("barrier.cluster.arrive.aligned;" ::: "memory");

        // overlap the trajectory store with peers' arrival skew
        g_hall[((size_t)t * LIQ + j0 + jl) * BATCH + g * 4 + b] = h;

        asm volatile("barrier.cluster.wait.aligned;" ::: "memory");
    }
}

// ---------------- stage 3: readout (byte-identical to passing R12) -----------------
__global__ void __launch_bounds__(256) readout_kernel(const float* __restrict__ Wro,
                                                      const float* __restrict__ bro,
                                                      float* __restrict__ out,
                                                      int write_hfinal) {
    extern __shared__ float sm[];
    float* hs = sm;            // [512][64]
    float* ws = sm + 32768;    // [512][32]
    const int t = blockIdx.x, tid = threadIdx.x;

    float4* hs4 = (float4*)hs;
    const float4* hall4 = (const float4*)g_hall + (size_t)t * 8192;
    for (int m = tid; m < 8192; m += 256) hs4[m] = hall4[m];

    const float4* Wro4 = (const float4*)Wro;
    float4* ws4 = (float4*)ws;
    const int oo = tid & 31, bg = tid >> 5;

    for (int ot = 0; ot < 4; ot++) {
        __syncthreads();
        for (int m = tid; m < 4096; m += 256) {
            int j = m >> 3, o4 = m & 7;
            ws4[m] = Wro4[j * 32 + ot * 8 + o4];
        }
        __syncthreads();

        int o = ot * 32 + oo;
        float bias = bro[o];
        float acc[8];
#pragma unroll
        for (int i = 0; i < 8; i++) acc[i] = 0.f;

        for (int k = 0; k < 512; k++) {
            float  w  = ws[k * 32 + oo];
            float4 h0 = hs4[k * 16 + bg * 2];
            float4 h1 = hs4[k * 16 + bg * 2 + 1];
            acc[0] += h0.x * w;  acc[1] += h0.y * w;
            acc[2] += h0.z * w;  acc[3] += h0.w * w;
            acc[4] += h1.x * w;  acc[5] += h1.y * w;
            acc[6] += h1.z * w;  acc[7] += h1.w * w;
        }
#pragma unroll
        for (int i = 0; i < 8; i++) {
            int b = bg * 8 + i;
            out[((size_t)b * T_STEPS + t) * OUT_DIM + o] = acc[i] + bias;
        }
    }

    if (t == T_STEPS - 1 && write_hfinal) {
        __syncthreads();
        const size_t FBASE = (size_t)BATCH * T_STEPS * OUT_DIM;
        for (int m = tid; m < BATCH * LIQ; m += 256) {
            int b = m >> 9, j = m & 511;
            out[FBASE + m] = hs[j * 64 + b];
        }
    }
}

// ---------------- launch ----------------
extern "C" void kernel_launch(void* const* d_in, const int* in_sizes, int n_in,
                              void* d_out, int out_size) {
    const float* inp = nullptr;
    const float* W   = nullptr;
    const float* Wro = nullptr;
    const float* bro = nullptr;
    for (int i = 0; i < n_in; i++) {
        switch (in_sizes[i]) {
            case 16777216: inp = (const float*)d_in[i]; break;
            case 327680:   W   = (const float*)d_in[i]; break;
            case 65536:    Wro = (const float*)d_in[i]; break;
            case 128:      bro = (const float*)d_in[i]; break;
            default: break;
        }
    }
    float* out = (float*)d_out;
    int write_hfinal = (out_size >= BATCH * T_STEPS * OUT_DIM + BATCH * LIQ) ? 1 : 0;

    const int XW_SMEM    = (8192 + 16896) * 4;    // 100352 B
    const int RECUR_SMEM = (33024 + 4128) * 4;    // 148608 B

    cudaFuncSetAttribute(xw_kernel,      cudaFuncAttributeMaxDynamicSharedMemorySize, XW_SMEM);
    cudaFuncSetAttribute(recur_kernel,   cudaFuncAttributeMaxDynamicSharedMemorySize, RECUR_SMEM);
    cudaFuncSetAttribute(readout_kernel, cudaFuncAttributeMaxDynamicSharedMemorySize, 196608);

    xw_kernel<<<T_STEPS, 512, XW_SMEM>>>(inp, W);
    recur_kernel<<<NG * GSZ, 256, RECUR_SMEM>>>(W);
    readout_kernel<<<T_STEPS, 256, 196608>>>(Wro, bro, out, write_hfinal);
}

// round 16
// speedup vs baseline: 1.7903x; 1.7427x over previous
#include <cuda_runtime.h>
#include <math.h>
#include <stdint.h>

#define T_STEPS 2048
#define BATCH   64
#define IN_DIM  128
#define LIQ     512
#define OUT_DIM 128
#define NG      16      // independent groups (4 batches each)
#define GSZ     8       // CTAs per group (64 j's each)

typedef unsigned long long ull;

// ---------------- scratch (device globals; no runtime allocation) ----------------
__device__ float g_xw2 [(size_t)T_STEPS * NG * LIQ * 4];   // [t][g][j][4b]
__device__ float g_hall[(size_t)T_STEPS * LIQ * BATCH];    // [t][j][b]
__device__ __align__(16) ull g_hxq[2][NG][1024];           // [buf][g][bp*512 + j] = (h_b0,h_b1)
__device__ unsigned g_cnt[T_STEPS * NG];                   // per-step group arrivals

// ---------------- XLA EmitFastTanh, with_fma=true configuration (BIT-EXACT) --------
__device__ __forceinline__ float xla_tanhf(float x) {
    const float kClamp = 7.99881172180175781f;
    float xc = fminf(fmaxf(x, -kClamp), kClamp);
    float x2 = __fmul_rn(xc, xc);
    float p = fmaf(x2, -2.76076847742355e-16f, 2.00018790482477e-13f);
    p = fmaf(x2, p, -8.60467152213735e-11f);
    p = fmaf(x2, p,  5.12229709037114e-08f);
    p = fmaf(x2, p,  1.48572235717979e-05f);
    p = fmaf(x2, p,  6.37261928875436e-04f);
    p = fmaf(x2, p,  4.89352455891786e-03f);
    float num = __fmul_rn(xc, p);
    float q = fmaf(x2, 1.19825839466702e-06f, 1.18534705686654e-04f);
    q = fmaf(x2, q, 2.26843463243900e-03f);
    q = fmaf(x2, q, 4.89352518554385e-03f);
    float r = __fdiv_rn(num, q);
    return (fabsf(x) < 0.0004f) ? x : r;
}

// packed dual-FMA: the two f32 lanes are INDEPENDENT correctly-rounded FMAs
#define FMA2(acc, h2, w2) \
    asm("fma.rn.f32x2 %0, %1, %2, %0;" : "+l"(acc) : "l"(h2), "l"(w2))
#define PACK_DUP(w2, f) \
    asm("mov.b64 %0, {%1, %1};" : "=l"(w2) : "r"(__float_as_uint(f)))

// ---------------- stage 1: xw = x_t @ W_x (byte-identical to passing R12) ----------
__global__ void __launch_bounds__(512) xw_kernel(const float* __restrict__ inp,
                                                 const float* __restrict__ W) {
    extern __shared__ float sm[];
    float* xs = sm;           // [64][128]   8192 floats
    float* wt = sm + 8192;    // [128 j][132 k] transposed W_x tile, 16896 floats
    const int t = blockIdx.x, tid = threadIdx.x;

    const float4* in4 = (const float4*)inp;
    float4* xs4 = (float4*)xs;
    for (int m = tid; m < 2048; m += 512) {
        int b = m >> 5, k4 = m & 31;
        xs4[m] = in4[((size_t)b * T_STEPS + t) * 32 + k4];
    }

    const int jl = tid & 127, bq = tid >> 7;

    for (int jt = 0; jt < 4; jt++) {
        __syncthreads();
        for (int i = tid; i < 16384; i += 512) {            // wt[j][k] = W_x[k][jt*128+j]
            int k = i >> 7, jj = i & 127;
            wt[jj * 132 + k] = W[(size_t)k * LIQ + jt * 128 + jj];
        }
        __syncthreads();

        const float* wrow = &wt[jl * 132];
        const int j = jt * 128 + jl;
        for (int ii = 0; ii < 16; ii++) {
            int b = bq * 16 + ii;
            const float* xrow = &xs[b * 128];
            float acc = 0.f;
#pragma unroll
            for (int k = 0; k < 128; k += 4) {              // ascending k, single acc
                float4 xv = *(const float4*)&xrow[k];
                float4 wv = *(const float4*)&wrow[k];
                acc = fmaf(xv.x, wv.x, acc);
                acc = fmaf(xv.y, wv.y, acc);
                acc = fmaf(xv.z, wv.z, acc);
                acc = fmaf(xv.w, wv.w, acc);
            }
            g_xw2[(((size_t)t * NG + (b >> 2)) * LIQ + j) * 4 + (b & 3)] = acc;
        }
    }
}

// ---------------- init ----------------
__global__ void __launch_bounds__(256) init_kernel() {
    int idx = blockIdx.x * 256 + threadIdx.x;    // grid 256 -> 65536
    if (idx < 2 * NG * 1024) ((ull*)g_hxq)[idx] = 0ULL;
    if (idx < T_STEPS * NG) g_cnt[idx] = 0u;
}

// ---------------- stage 2: recurrence — f32x2 dual-batch chains, R12 exchange -------
// CTA (g = bid>>3, r = bid&7): batches 4g..4g+3, j in [64r, 64r+64).
// 128 threads: jl = tid&63 (j), bp = tid>>6 (batch pair 2bp, 2bp+1).
// Each thread runs TWO independent ascending-k single-accumulator FMA chains in
// the two f32 lanes of fma.rn.f32x2 — each lane's rounding sequence is IDENTICAL
// to the passing R12 scalar chain (bit-exact by construction).
__global__ void __launch_bounds__(128, 1) recur_kernel(const float* __restrict__ W) {
    extern __shared__ float smem[];
    float* Wt   = smem;                  // [64 j][516 k]  33024 floats
    ull*   hsmq = (ull*)(smem + 33024);  // [2 bp][512 k] (b0,b1) pairs, 1024 ull

    const int tid = threadIdx.x;
    const int g   = (int)(blockIdx.x >> 3);
    const int r   = (int)(blockIdx.x & 7);
    const int j0  = r * 64;

    for (int i = tid; i < 64 * LIQ; i += 128) {              // Wt[j][k] = W[128+k][j0+j]
        int k = i >> 6, jj = i & 63;
        Wt[jj * 516 + k] = W[(size_t)(128 + k) * LIQ + j0 + jj];
    }

    const int jl = tid & 63;
    const int bp = tid >> 6;
    const float* wrow = &Wt[jl * 516];
    const ull*   hrow = &hsmq[bp * 512];

    for (int t = 0; t < T_STEPS; t++) {
        if (t > 0 && tid == 0) {
            unsigned* cp = &g_cnt[(size_t)(t - 1) * NG + g];
            while (atomicAdd(cp, 0u) != (unsigned)GSZ) { }   // RMW read: L2-coherent
        }
        __syncthreads();                                     // bar A (Wt ready at t==0)

        {   // pull group's h pairs (1024 ull = 8 KB) into SMEM, fresh from L2
            const ull* src = g_hxq[t & 1][g];
#pragma unroll
            for (int q = 0; q < 8; q++) {
                int idx = q * 128 + tid;
                hsmq[idx] = __ldcv(&src[idx]);
            }
        }
        float2 xwv = *(const float2*)&g_xw2[(((size_t)t * NG + g) * LIQ + j0 + jl) * 4 + 2 * bp];
        __syncthreads();                                     // bar B: hsm ready

        ull acc = 0ULL;                                      // (0.f, 0.f)
#pragma unroll 16
        for (int k = 0; k < 512; k += 4) {                   // ascending k, per-lane serial
            float4 wv = *(const float4*)&wrow[k];
            ulonglong2 hA = *(const ulonglong2*)&hrow[k];        // pairs k, k+1
            ulonglong2 hB = *(const ulonglong2*)&hrow[k + 2];    // pairs k+2, k+3
            ull w2;
            PACK_DUP(w2, wv.x);  FMA2(acc, hA.x, w2);
            PACK_DUP(w2, wv.y);  FMA2(acc, hA.y, w2);
            PACK_DUP(w2, wv.z);  FMA2(acc, hB.x, w2);
            PACK_DUP(w2, wv.w);  FMA2(acc, hB.y, w2);
        }
        float a0, a1;
        asm("mov.b64 {%0, %1}, %2;" : "=f"(a0), "=f"(a1) : "l"(acc));

        float h0 = xla_tanhf(__fadd_rn(xwv.x, a0));          // b = 2bp   (chain == R12)
        float h1 = xla_tanhf(__fadd_rn(xwv.y, a1));          // b = 2bp+1 (chain == R12)

        *(float2*)&g_hall[((size_t)t * LIQ + j0 + jl) * BATCH + g * 4 + 2 * bp] =
            make_float2(h0, h1);
        {
            float2 hv = make_float2(h0, h1);
            g_hxq[(t + 1) & 1][g][bp * 512 + j0 + jl] = *(ull*)&hv;
        }

        __threadfence();                                     // release (every thread)
        __syncthreads();                                     // bar C: stores done
        if (tid == 0)
            atomicAdd(&g_cnt[(size_t)t * NG + g], 1u);
    }
}

// ---------------- stage 3: readout (byte-identical to passing R12) -----------------
__global__ void __launch_bounds__(256) readout_kernel(const float* __restrict__ Wro,
                                                      const float* __restrict__ bro,
                                                      float* __restrict__ out,
                                                      int write_hfinal) {
    extern __shared__ float sm[];
    float* hs = sm;            // [512][64]
    float* ws = sm + 32768;    // [512][32]
    const int t = blockIdx.x, tid = threadIdx.x;

    float4* hs4 = (float4*)hs;
    const float4* hall4 = (const float4*)g_hall + (size_t)t * 8192;
    for (int m = tid; m < 8192; m += 256) hs4[m] = hall4[m];

    const float4* Wro4 = (const float4*)Wro;
    float4* ws4 = (float4*)ws;
    const int oo = tid & 31, bg = tid >> 5;

    for (int ot = 0; ot < 4; ot++) {
        __syncthreads();
        for (int m = tid; m < 4096; m += 256) {
            int j = m >> 3, o4 = m & 7;
            ws4[m] = Wro4[j * 32 + ot * 8 + o4];
        }
        __syncthreads();

        int o = ot * 32 + oo;
        float bias = bro[o];
        float acc[8];
#pragma unroll
        for (int i = 0; i < 8; i++) acc[i] = 0.f;

        for (int k = 0; k < 512; k++) {
            float  w  = ws[k * 32 + oo];
            float4 h0 = hs4[k * 16 + bg * 2];
            float4 h1 = hs4[k * 16 + bg * 2 + 1];
            acc[0] += h0.x * w;  acc[1] += h0.y * w;
            acc[2] += h0.z * w;  acc[3] += h0.w * w;
            acc[4] += h1.x * w;  acc[5] += h1.y * w;
            acc[6] += h1.z * w;  acc[7] += h1.w * w;
        }
#pragma unroll
        for (int i = 0; i < 8; i++) {
            int b = bg * 8 + i;
            out[((size_t)b * T_STEPS + t) * OUT_DIM + o] = acc[i] + bias;
        }
    }

    if (t == T_STEPS - 1 && write_hfinal) {
        __syncthreads();
        const size_t FBASE = (size_t)BATCH * T_STEPS * OUT_DIM;
        for (int m = tid; m < BATCH * LIQ; m += 256) {
            int b = m >> 9, j = m & 511;
            out[FBASE + m] = hs[j * 64 + b];
        }
    }
}

// ---------------- launch ----------------
extern "C" void kernel_launch(void* const* d_in, const int* in_sizes, int n_in,
                              void* d_out, int out_size) {
    const float* inp = nullptr;
    const float* W   = nullptr;
    const float* Wro = nullptr;
    const float* bro = nullptr;
    for (int i = 0; i < n_in; i++) {
        switch (in_sizes[i]) {
            case 16777216: inp = (const float*)d_in[i]; break;
            case 327680:   W   = (const float*)d_in[i]; break;
            case 65536:    Wro = (const float*)d_in[i]; break;
            case 128:      bro = (const float*)d_in[i]; break;
            default: break;
        }
    }
    float* out = (float*)d_out;
    int write_hfinal = (out_size >= BATCH * T_STEPS * OUT_DIM + BATCH * LIQ) ? 1 : 0;

    const int XW_SMEM    = (8192 + 16896) * 4;    // 100352 B
    const int RECUR_SMEM = 33024 * 4 + 1024 * 8;  // 140288 B

    cudaFuncSetAttribute(xw_kernel,      cudaFuncAttributeMaxDynamicSharedMemorySize, XW_SMEM);
    cudaFuncSetAttribute(recur_kernel,   cudaFuncAttributeMaxDynamicSharedMemorySize, RECUR_SMEM);
    cudaFuncSetAttribute(readout_kernel, cudaFuncAttributeMaxDynamicSharedMemorySize, 196608);

    xw_kernel<<<T_STEPS, 512, XW_SMEM>>>(inp, W);
    init_kernel<<<256, 256>>>();
    recur_kernel<<<NG * GSZ, 128, RECUR_SMEM>>>(W);
    readout_kernel<<<T_STEPS, 256, 196608>>>(Wro, bro, out, write_hfinal);
}